// round 14
// baseline (speedup 1.0000x reference)
#include <cuda_runtime.h>
#include <cuda_fp16.h>
#include <math.h>
#include <stdint.h>

// Problem constants (fixed by the dataset)
#define NMAX   100032
#define EMAX   1600000
#define DIMF   128
#define DV4    32

// Static scratch
__device__ __half2 g_tab[NMAX * 64];    // scaled features fp16 (gather table)
__device__ __half2 g_aggh[NMAX * 64];   // gathered+c_dst-scaled rows, fp16
__device__ __half  g_W16[3 * DIMF * DIMF]; // fp16 n-major weights (k contiguous)
__device__ float   g_csrc[NMAX];
__device__ float   g_cdst[NMAX];
__device__ int     g_deg[2 * NMAX];     // raw degrees: [0..n) out, [n..2n) in
__device__ int     g_off[NMAX];         // CSR range start (order-free)
__device__ int     g_cursor[NMAX];
__device__ int     g_csr_src[EMAX];
__device__ int     g_ctr;               // global range allocator

static inline int cdiv(int a, int b) { return (a + b - 1) / b; }

// ---------------------------------------------------------------------------
// W prep: fp32 k-major [k][n] -> fp16 n-major [n][k], one-time.
// ---------------------------------------------------------------------------
__global__ void k_prepW(const float* __restrict__ W0,
                        const float* __restrict__ W1,
                        const float* __restrict__ W2) {
    __shared__ float t[64][65];
    const float* W = (blockIdx.z == 0) ? W0 : (blockIdx.z == 1) ? W1 : W2;
    __half* out = g_W16 + blockIdx.z * DIMF * DIMF;
    const int tid = threadIdx.x;
    const int kt = blockIdx.x * 64;
    const int nt = blockIdx.y * 64;

#pragma unroll
    for (int it = 0; it < 4; it++) {
        int i  = tid + it * 256;
        int r  = i >> 4;
        int c4 = i & 15;
        float4 v = __ldg(&((const float4*)W)[(kt + r) * DV4 + blockIdx.y * 16 + c4]);
        t[r][c4 * 4 + 0] = v.x;
        t[r][c4 * 4 + 1] = v.y;
        t[r][c4 * 4 + 2] = v.z;
        t[r][c4 * 4 + 3] = v.w;
    }
    __syncthreads();
#pragma unroll
    for (int it = 0; it < 4; it++) {
        int i  = tid + it * 256;
        int r  = i >> 4;
        int c4 = i & 15;
        __half2 h0 = __floats2half2_rn(t[c4 * 4 + 0][r], t[c4 * 4 + 1][r]);
        __half2 h1 = __floats2half2_rn(t[c4 * 4 + 2][r], t[c4 * 4 + 3][r]);
        uint2 o;
        o.x = *(uint32_t*)&h0;
        o.y = *(uint32_t*)&h1;
        *(uint2*)(out + (nt + r) * DIMF + kt + c4 * 4) = o;
    }
}

// ---------------------------------------------------------------------------
// Degree count, x4 vectorized (g_deg pre-zeroed by memset)
// ---------------------------------------------------------------------------
__global__ void k_deg_count(const int* __restrict__ ei, int E, int n) {
    int i = blockIdx.x * blockDim.x + threadIdx.x;
    if (i * 4 < E) {
        int4 s = ((const int4*)ei)[i];
        int4 d = ((const int4*)(ei + E))[i];
        atomicAdd(&g_deg[s.x], 1);
        atomicAdd(&g_deg[s.y], 1);
        atomicAdd(&g_deg[s.z], 1);
        atomicAdd(&g_deg[s.w], 1);
        atomicAdd(&g_deg[n + d.x], 1);
        atomicAdd(&g_deg[n + d.y], 1);
        atomicAdd(&g_deg[n + d.z], 1);
        atomicAdd(&g_deg[n + d.w], 1);
    }
}

// ---------------------------------------------------------------------------
// k_offsets: order-free CSR range assignment + normalization coefs.
// Warp-scan of in-degrees, one global atomicAdd per warp. No prefix scan.
// ---------------------------------------------------------------------------
__global__ void k_offsets(int n) {
    int i = blockIdx.x * blockDim.x + threadIdx.x;
    int lane = threadIdx.x & 31;
    int d = (i < n) ? g_deg[n + i] : 0;

    // inclusive warp scan of d
    int scan = d;
#pragma unroll
    for (int o = 1; o < 32; o <<= 1) {
        int v = __shfl_up_sync(0xffffffffu, scan, o);
        if (lane >= o) scan += v;
    }
    int total = __shfl_sync(0xffffffffu, scan, 31);
    int base = 0;
    if (lane == 31) base = atomicAdd(&g_ctr, total);
    base = __shfl_sync(0xffffffffu, base, 31);
    int start = base + scan - d;   // exclusive position within warp

    if (i < n) {
        g_off[i] = start;
        g_cursor[i] = start;
        g_csrc[i] = rsqrtf((float)(g_deg[i] + 1));  // +1 self loop
        g_cdst[i] = rsqrtf((float)(d + 1));
    }
}

// CSR fill, x4 vectorized
__global__ void k_fill(const int* __restrict__ ei, int E) {
    int i = blockIdx.x * blockDim.x + threadIdx.x;
    if (i * 4 < E) {
        int4 s = ((const int4*)ei)[i];
        int4 d = ((const int4*)(ei + E))[i];
        int p0 = atomicAdd(&g_cursor[d.x], 1);
        int p1 = atomicAdd(&g_cursor[d.y], 1);
        int p2 = atomicAdd(&g_cursor[d.z], 1);
        int p3 = atomicAdd(&g_cursor[d.w], 1);
        g_csr_src[p0] = s.x;
        g_csr_src[p1] = s.y;
        g_csr_src[p2] = s.z;
        g_csr_src[p3] = s.w;
    }
}

// ---------------------------------------------------------------------------
// Layer-1 scale: g_tab = fp16(node_attr * c_src[row])
// ---------------------------------------------------------------------------
__global__ void k_scale(const float* __restrict__ x, int n) {
    int idx = blockIdx.x * blockDim.x + threadIdx.x;
    if (idx < n * DV4) {
        int row = idx >> 5;
        float c = g_csrc[row];
        float4 v = ((const float4*)x)[idx];
        __half2 h0 = __floats2half2_rn(v.x * c, v.y * c);
        __half2 h1 = __floats2half2_rn(v.z * c, v.w * c);
        uint2 o;
        o.x = *(uint32_t*)&h0;
        o.y = *(uint32_t*)&h1;
        ((uint2*)g_tab)[idx] = o;
    }
}

// ---------------------------------------------------------------------------
// Gather: g_aggh[d,:] = fp16( c_dst[d] * (tab[d,:] + sum_{s in in(d)} tab[s,:]) )
// 16 lanes per node, fp32 accumulation, unroll-8 edges (16 x 256B in flight).
// ---------------------------------------------------------------------------
__device__ __forceinline__ void acc8(float* a, uint4 u) {
    const __half2* hp = (const __half2*)&u;
#pragma unroll
    for (int q = 0; q < 4; q++) {
        float2 f = __half22float2(hp[q]);
        a[2 * q]     += f.x;
        a[2 * q + 1] += f.y;
    }
}

__global__ void __launch_bounds__(256)
k_gather(int n) {
    int t = blockIdx.x * blockDim.x + threadIdx.x;
    int node = t >> 4;
    int l16  = t & 15;
    if (node >= n) return;

    const uint4* tab = (const uint4*)g_tab;
    float a[8] = {0.f, 0.f, 0.f, 0.f, 0.f, 0.f, 0.f, 0.f};
    acc8(a, __ldg(&tab[node * 16 + l16]));   // self loop

    int j   = g_off[node];
    int end = j + __ldg(&g_deg[n + node]);

    for (; j + 8 <= end; j += 8) {
        int s0 = __ldg(&g_csr_src[j]);
        int s1 = __ldg(&g_csr_src[j + 1]);
        int s2 = __ldg(&g_csr_src[j + 2]);
        int s3 = __ldg(&g_csr_src[j + 3]);
        int s4 = __ldg(&g_csr_src[j + 4]);
        int s5 = __ldg(&g_csr_src[j + 5]);
        int s6 = __ldg(&g_csr_src[j + 6]);
        int s7 = __ldg(&g_csr_src[j + 7]);
        uint4 v0 = __ldg(&tab[s0 * 16 + l16]);
        uint4 v1 = __ldg(&tab[s1 * 16 + l16]);
        uint4 v2 = __ldg(&tab[s2 * 16 + l16]);
        uint4 v3 = __ldg(&tab[s3 * 16 + l16]);
        uint4 v4 = __ldg(&tab[s4 * 16 + l16]);
        uint4 v5 = __ldg(&tab[s5 * 16 + l16]);
        uint4 v6 = __ldg(&tab[s6 * 16 + l16]);
        uint4 v7 = __ldg(&tab[s7 * 16 + l16]);
        acc8(a, v0); acc8(a, v1); acc8(a, v2); acc8(a, v3);
        acc8(a, v4); acc8(a, v5); acc8(a, v6); acc8(a, v7);
    }
    for (; j < end; j++) {
        int s = __ldg(&g_csr_src[j]);
        acc8(a, __ldg(&tab[s * 16 + l16]));
    }

    float cd = g_cdst[node];
#pragma unroll
    for (int q = 0; q < 8; q++) a[q] *= cd;

    __half2 h0 = __floats2half2_rn(a[0], a[1]);
    __half2 h1 = __floats2half2_rn(a[2], a[3]);
    __half2 h2 = __floats2half2_rn(a[4], a[5]);
    __half2 h3 = __floats2half2_rn(a[6], a[7]);
    uint4 pk = make_uint4(*(uint32_t*)&h0, *(uint32_t*)&h1,
                          *(uint32_t*)&h2, *(uint32_t*)&h3);
    ((uint4*)g_aggh)[node * 16 + l16] = pk;
}

// ---------------------------------------------------------------------------
// fp16 GEMM (m16n8k16): y = aggh @ W + b ; full K=128 in smem.
// ---------------------------------------------------------------------------
#define SROW 68   // smem row stride in words (136 halves)

__device__ __forceinline__ void mma_f16(float* c, const uint32_t* a,
                                        uint32_t b0, uint32_t b1) {
    asm volatile(
        "mma.sync.aligned.m16n8k16.row.col.f32.f16.f16.f32 "
        "{%0,%1,%2,%3}, {%4,%5,%6,%7}, {%8,%9}, {%0,%1,%2,%3};"
        : "+f"(c[0]), "+f"(c[1]), "+f"(c[2]), "+f"(c[3])
        : "r"(a[0]), "r"(a[1]), "r"(a[2]), "r"(a[3]), "r"(b0), "r"(b1));
}

template <bool WRITE_SCALED>
__global__ void __launch_bounds__(256)
k_gemm(const __half* __restrict__ W16, const float* __restrict__ b,
       float* __restrict__ out, int n) {
    extern __shared__ uint32_t smem[];
    uint32_t* As = smem;                 // 128 x 68 words (fp16 rows)
    uint32_t* Bs = smem + 128 * SROW;    // 128 x 68 words (W^T, n-major fp16)

    const int tid  = threadIdx.x;
    const int warp = tid >> 5;
    const int lane = tid & 31;
    const int g    = lane >> 2;
    const int t4   = lane & 3;
    const int rowBase = blockIdx.x * 128;
    const int warpRow = warp * 16;

    // ---- A: copy 128 fp16 rows from g_aggh ----
    {
        const uint4* src = (const uint4*)g_aggh;
#pragma unroll
        for (int it = 0; it < 8; it++) {
            int i  = tid + it * 256;
            int r  = i >> 4;
            int c4 = i & 15;
            int gr = rowBase + r;
            uint4 v = make_uint4(0u, 0u, 0u, 0u);
            if (gr < n) v = __ldg(&src[gr * 16 + c4]);
            ((uint4*)As)[r * (SROW / 4) + c4] = v;
        }
    }
    // ---- B: copy prepped fp16 n-major W ----
    {
        const uint4* src = (const uint4*)W16;
#pragma unroll
        for (int it = 0; it < 8; it++) {
            int i  = tid + it * 256;
            int r  = i >> 4;
            int c4 = i & 15;
            ((uint4*)Bs)[r * (SROW / 4) + c4] = __ldg(&src[r * 16 + c4]);
        }
    }
    __syncthreads();

    // ---- mma mainloop ----
    float acc[16][4];
#pragma unroll
    for (int nt = 0; nt < 16; nt++) {
        float b0v = __ldg(&b[nt * 8 + t4 * 2]);
        float b1v = __ldg(&b[nt * 8 + t4 * 2 + 1]);
        acc[nt][0] = b0v; acc[nt][1] = b1v;
        acc[nt][2] = b0v; acc[nt][3] = b1v;
    }

#pragma unroll
    for (int kc = 0; kc < 8; kc++) {
        uint32_t a[4];
        const int a0 = (warpRow + g) * SROW + kc * 8 + t4;
        const int a1 = a0 + 8 * SROW;
        a[0] = As[a0];
        a[1] = As[a1];
        a[2] = As[a0 + 4];
        a[3] = As[a1 + 4];
#pragma unroll
        for (int nt = 0; nt < 16; nt++) {
            const int bo = (nt * 8 + g) * SROW + kc * 8 + t4;
            mma_f16(acc[nt], a, Bs[bo], Bs[bo + 4]);
        }
    }

    // ---- epilogue ----
    const int r0 = rowBase + warpRow + g;
    const int r1 = r0 + 8;
#pragma unroll
    for (int nt = 0; nt < 16; nt++) {
        const int col = nt * 8 + t4 * 2;
        if (WRITE_SCALED) {
            if (r0 < n) {
                float cs = g_csrc[r0];
                g_tab[r0 * 64 + (col >> 1)] =
                    __floats2half2_rn(fmaxf(acc[nt][0], 0.f) * cs,
                                      fmaxf(acc[nt][1], 0.f) * cs);
            }
            if (r1 < n) {
                float cs = g_csrc[r1];
                g_tab[r1 * 64 + (col >> 1)] =
                    __floats2half2_rn(fmaxf(acc[nt][2], 0.f) * cs,
                                      fmaxf(acc[nt][3], 0.f) * cs);
            }
        } else {
            if (r0 < n)
                *(float2*)&out[r0 * DIMF + col] = make_float2(acc[nt][0], acc[nt][1]);
            if (r1 < n)
                *(float2*)&out[r1 * DIMF + col] = make_float2(acc[nt][2], acc[nt][3]);
        }
    }
}

// ---------------------------------------------------------------------------

#define SMEM_BYTES (2 * 128 * SROW * 4)   // 69632

extern "C" void kernel_launch(void* const* d_in, const int* in_sizes, int n_in,
                              void* d_out, int out_size) {
    const float* node_attr = (const float*)d_in[0];
    const float* W0 = (const float*)d_in[1];
    const float* b0 = (const float*)d_in[2];
    const float* W1 = (const float*)d_in[3];
    const float* b1 = (const float*)d_in[4];
    const float* W2 = (const float*)d_in[5];
    const float* b2 = (const float*)d_in[6];
    const int*   edge = (const int*)d_in[7];

    int n = in_sizes[0] / DIMF;   // 100000
    int E = in_sizes[7] / 2;      // 1600000

    cudaFuncSetAttribute(k_gemm<true>,
                         cudaFuncAttributeMaxDynamicSharedMemorySize, SMEM_BYTES);
    cudaFuncSetAttribute(k_gemm<false>,
                         cudaFuncAttributeMaxDynamicSharedMemorySize, SMEM_BYTES);

    // one-time W conversion (independent of graph work)
    k_prepW<<<dim3(2, 2, 3), 256>>>(W0, W1, W2);

    // zero degree array + range allocator
    void* degPtr;
    cudaGetSymbolAddress(&degPtr, g_deg);
    cudaMemsetAsync(degPtr, 0, 2 * n * sizeof(int));
    void* ctrPtr;
    cudaGetSymbolAddress(&ctrPtr, g_ctr);
    cudaMemsetAsync(ctrPtr, 0, sizeof(int));

    k_deg_count<<<cdiv(E / 4, 256), 256>>>(edge, E, n);
    k_offsets<<<cdiv(n, 256), 256>>>(n);
    k_fill<<<cdiv(E / 4, 256), 256>>>(edge, E);

    // layer-1 table
    k_scale<<<cdiv(n * DV4, 256), 256>>>(node_attr, n);

    __half* w16;
    cudaGetSymbolAddress((void**)&w16, g_W16);

    int ggrid = cdiv(n * 16, 256);
    int mgrid = cdiv(n, 128);

    k_gather<<<ggrid, 256>>>(n);
    k_gemm<true><<<mgrid, 256, SMEM_BYTES>>>(w16, b0, nullptr, n);
    k_gather<<<ggrid, 256>>>(n);
    k_gemm<true><<<mgrid, 256, SMEM_BYTES>>>(w16 + DIMF * DIMF, b1, nullptr, n);
    k_gather<<<ggrid, 256>>>(n);
    k_gemm<false><<<mgrid, 256, SMEM_BYTES>>>(w16 + 2 * DIMF * DIMF, b2, (float*)d_out, n);
}

// round 15
// speedup vs baseline: 1.0392x; 1.0392x over previous
#include <cuda_runtime.h>
#include <cuda_fp16.h>
#include <math.h>
#include <stdint.h>

// Problem constants (fixed by the dataset)
#define NMAX   100032
#define EMAX   1600000
#define DIMF   128
#define DV4    32

// Static scratch
__device__ __half2 g_tab[NMAX * 64];    // scaled features fp16 (gather table)
__device__ __half2 g_aggh[NMAX * 64];   // gathered+c_dst-scaled rows, fp16
__device__ __half  g_W16[3 * DIMF * DIMF]; // fp16 n-major weights (k contiguous)
__device__ float   g_csrc[NMAX];
__device__ float   g_cdst[NMAX];
__device__ int     g_deg[2 * NMAX + 1]; // [0..n) out, [n..2n) in, [2n] = allocator
__device__ int     g_off[NMAX];         // CSR range start (order-free)
__device__ int     g_cursor[NMAX];
__device__ int     g_csr_src[EMAX];

static inline int cdiv(int a, int b) { return (a + b - 1) / b; }

// ---------------------------------------------------------------------------
// W prep: fp32 k-major [k][n] -> fp16 n-major [n][k], one-time.
// ---------------------------------------------------------------------------
__global__ void k_prepW(const float* __restrict__ W0,
                        const float* __restrict__ W1,
                        const float* __restrict__ W2) {
    __shared__ float t[64][65];
    const float* W = (blockIdx.z == 0) ? W0 : (blockIdx.z == 1) ? W1 : W2;
    __half* out = g_W16 + blockIdx.z * DIMF * DIMF;
    const int tid = threadIdx.x;
    const int kt = blockIdx.x * 64;
    const int nt = blockIdx.y * 64;

#pragma unroll
    for (int it = 0; it < 4; it++) {
        int i  = tid + it * 256;
        int r  = i >> 4;
        int c4 = i & 15;
        float4 v = __ldg(&((const float4*)W)[(kt + r) * DV4 + blockIdx.y * 16 + c4]);
        t[r][c4 * 4 + 0] = v.x;
        t[r][c4 * 4 + 1] = v.y;
        t[r][c4 * 4 + 2] = v.z;
        t[r][c4 * 4 + 3] = v.w;
    }
    __syncthreads();
#pragma unroll
    for (int it = 0; it < 4; it++) {
        int i  = tid + it * 256;
        int r  = i >> 4;
        int c4 = i & 15;
        __half2 h0 = __floats2half2_rn(t[c4 * 4 + 0][r], t[c4 * 4 + 1][r]);
        __half2 h1 = __floats2half2_rn(t[c4 * 4 + 2][r], t[c4 * 4 + 3][r]);
        uint2 o;
        o.x = *(uint32_t*)&h0;
        o.y = *(uint32_t*)&h1;
        *(uint2*)(out + (nt + r) * DIMF + kt + c4 * 4) = o;
    }
}

// ---------------------------------------------------------------------------
// Degree count, scalar (R12-proven faster than int4 form on this kernel)
// ---------------------------------------------------------------------------
__global__ void k_deg_count(const int* __restrict__ ei, int E, int n) {
    int i = blockIdx.x * blockDim.x + threadIdx.x;
    if (i < E) {
        atomicAdd(&g_deg[ei[i]], 1);
        atomicAdd(&g_deg[n + ei[E + i]], 1);
    }
}

// ---------------------------------------------------------------------------
// k_offsets: order-free CSR range assignment + normalization coefs.
// Warp-scan of in-degrees, one global atomicAdd per warp (allocator at g_deg[2n]).
// ---------------------------------------------------------------------------
__global__ void k_offsets(int n) {
    int i = blockIdx.x * blockDim.x + threadIdx.x;
    int lane = threadIdx.x & 31;
    int d = (i < n) ? g_deg[n + i] : 0;

    int scan = d;
#pragma unroll
    for (int o = 1; o < 32; o <<= 1) {
        int v = __shfl_up_sync(0xffffffffu, scan, o);
        if (lane >= o) scan += v;
    }
    int total = __shfl_sync(0xffffffffu, scan, 31);
    int base = 0;
    if (lane == 31) base = atomicAdd(&g_deg[2 * n], total);
    base = __shfl_sync(0xffffffffu, base, 31);
    int start = base + scan - d;

    if (i < n) {
        g_off[i] = start;
        g_cursor[i] = start;
        g_csrc[i] = rsqrtf((float)(g_deg[i] + 1));  // +1 self loop
        g_cdst[i] = rsqrtf((float)(d + 1));
    }
}

// CSR fill, scalar (R12-proven)
__global__ void k_fill(const int* __restrict__ ei, int E) {
    int i = blockIdx.x * blockDim.x + threadIdx.x;
    if (i < E) {
        int s = ei[i];
        int d = ei[E + i];
        int pos = atomicAdd(&g_cursor[d], 1);
        g_csr_src[pos] = s;
    }
}

// ---------------------------------------------------------------------------
// Layer-1 scale: g_tab = fp16(node_attr * c_src[row])
// ---------------------------------------------------------------------------
__global__ void k_scale(const float* __restrict__ x, int n) {
    int idx = blockIdx.x * blockDim.x + threadIdx.x;
    if (idx < n * DV4) {
        int row = idx >> 5;
        float c = g_csrc[row];
        float4 v = ((const float4*)x)[idx];
        __half2 h0 = __floats2half2_rn(v.x * c, v.y * c);
        __half2 h1 = __floats2half2_rn(v.z * c, v.w * c);
        uint2 o;
        o.x = *(uint32_t*)&h0;
        o.y = *(uint32_t*)&h1;
        ((uint2*)g_tab)[idx] = o;
    }
}

// ---------------------------------------------------------------------------
// Gather: g_aggh[d,:] = fp16( c_dst[d] * (tab[d,:] + sum_{s in in(d)} tab[s,:]) )
// 16 lanes per node, fp32 accumulation, unroll-4 edges (R12-proven).
// ---------------------------------------------------------------------------
__device__ __forceinline__ void acc8(float* a, uint4 u) {
    const __half2* hp = (const __half2*)&u;
#pragma unroll
    for (int q = 0; q < 4; q++) {
        float2 f = __half22float2(hp[q]);
        a[2 * q]     += f.x;
        a[2 * q + 1] += f.y;
    }
}

__global__ void __launch_bounds__(256)
k_gather(int n) {
    int t = blockIdx.x * blockDim.x + threadIdx.x;
    int node = t >> 4;
    int l16  = t & 15;
    if (node >= n) return;

    const uint4* tab = (const uint4*)g_tab;
    float a[8] = {0.f, 0.f, 0.f, 0.f, 0.f, 0.f, 0.f, 0.f};
    acc8(a, __ldg(&tab[node * 16 + l16]));   // self loop

    int j   = g_off[node];
    int end = j + __ldg(&g_deg[n + node]);

    for (; j + 4 <= end; j += 4) {
        int s0 = __ldg(&g_csr_src[j]);
        int s1 = __ldg(&g_csr_src[j + 1]);
        int s2 = __ldg(&g_csr_src[j + 2]);
        int s3 = __ldg(&g_csr_src[j + 3]);
        uint4 v0 = __ldg(&tab[s0 * 16 + l16]);
        uint4 v1 = __ldg(&tab[s1 * 16 + l16]);
        uint4 v2 = __ldg(&tab[s2 * 16 + l16]);
        uint4 v3 = __ldg(&tab[s3 * 16 + l16]);
        acc8(a, v0); acc8(a, v1); acc8(a, v2); acc8(a, v3);
    }
    for (; j < end; j++) {
        int s = __ldg(&g_csr_src[j]);
        acc8(a, __ldg(&tab[s * 16 + l16]));
    }

    float cd = g_cdst[node];
#pragma unroll
    for (int q = 0; q < 8; q++) a[q] *= cd;

    __half2 h0 = __floats2half2_rn(a[0], a[1]);
    __half2 h1 = __floats2half2_rn(a[2], a[3]);
    __half2 h2 = __floats2half2_rn(a[4], a[5]);
    __half2 h3 = __floats2half2_rn(a[6], a[7]);
    uint4 pk = make_uint4(*(uint32_t*)&h0, *(uint32_t*)&h1,
                          *(uint32_t*)&h2, *(uint32_t*)&h3);
    ((uint4*)g_aggh)[node * 16 + l16] = pk;
}

// ---------------------------------------------------------------------------
// fp16 GEMM (m16n8k16): y = aggh @ W + b ; full K=128 in smem.
// Fragments loaded via ldmatrix.x4 (1 A + 8 B per kc instead of 36 LDS.32).
// ---------------------------------------------------------------------------
#define SROW 68   // smem row stride in words (136 halves); 8-row bank step = 4

__device__ __forceinline__ void mma_f16(float* c, const uint32_t* a,
                                        uint32_t b0, uint32_t b1) {
    asm volatile(
        "mma.sync.aligned.m16n8k16.row.col.f32.f16.f16.f32 "
        "{%0,%1,%2,%3}, {%4,%5,%6,%7}, {%8,%9}, {%0,%1,%2,%3};"
        : "+f"(c[0]), "+f"(c[1]), "+f"(c[2]), "+f"(c[3])
        : "r"(a[0]), "r"(a[1]), "r"(a[2]), "r"(a[3]), "r"(b0), "r"(b1));
}

#define LDMATRIX_X4(r0, r1, r2, r3, addr) \
    asm volatile("ldmatrix.sync.aligned.m8n8.x4.shared.b16 {%0,%1,%2,%3}, [%4];" \
        : "=r"(r0), "=r"(r1), "=r"(r2), "=r"(r3) : "r"(addr))

template <bool WRITE_SCALED>
__global__ void __launch_bounds__(256)
k_gemm(const __half* __restrict__ W16, const float* __restrict__ b,
       float* __restrict__ out, int n) {
    extern __shared__ uint32_t smem[];
    uint32_t* As = smem;                 // 128 x 68 words (fp16 rows)
    uint32_t* Bs = smem + 128 * SROW;    // 128 x 68 words (W^T, n-major fp16)

    const int tid  = threadIdx.x;
    const int warp = tid >> 5;
    const int lane = tid & 31;
    const int g    = lane >> 2;
    const int t4   = lane & 3;
    const int rowBase = blockIdx.x * 128;
    const int warpRow = warp * 16;

    // ---- A: copy 128 fp16 rows from g_aggh ----
    {
        const uint4* src = (const uint4*)g_aggh;
#pragma unroll
        for (int it = 0; it < 8; it++) {
            int i  = tid + it * 256;
            int r  = i >> 4;
            int c4 = i & 15;
            int gr = rowBase + r;
            uint4 v = make_uint4(0u, 0u, 0u, 0u);
            if (gr < n) v = __ldg(&src[gr * 16 + c4]);
            ((uint4*)As)[r * (SROW / 4) + c4] = v;
        }
    }
    // ---- B: copy prepped fp16 n-major W ----
    {
        const uint4* src = (const uint4*)W16;
#pragma unroll
        for (int it = 0; it < 8; it++) {
            int i  = tid + it * 256;
            int r  = i >> 4;
            int c4 = i & 15;
            ((uint4*)Bs)[r * (SROW / 4) + c4] = __ldg(&src[r * 16 + c4]);
        }
    }
    __syncthreads();

    // ---- fragment addresses (per-lane) ----
    const uint32_t As_sh = (uint32_t)__cvta_generic_to_shared(As);
    const uint32_t Bs_sh = (uint32_t)__cvta_generic_to_shared(Bs);
    const int lrow  = lane & 15;    // row within 16-row tile group
    const int khalf = lane >> 4;    // 0: k0-7, 1: k8-15
    const uint32_t a_base = As_sh + ((warpRow + lrow) * SROW + khalf * 4) * 4;

    // ---- mma mainloop ----
    float acc[16][4];
#pragma unroll
    for (int nt = 0; nt < 16; nt++) {
        float b0v = __ldg(&b[nt * 8 + t4 * 2]);
        float b1v = __ldg(&b[nt * 8 + t4 * 2 + 1]);
        acc[nt][0] = b0v; acc[nt][1] = b1v;
        acc[nt][2] = b0v; acc[nt][3] = b1v;
    }

#pragma unroll
    for (int kc = 0; kc < 8; kc++) {
        uint32_t a[4];
        LDMATRIX_X4(a[0], a[1], a[2], a[3], a_base + kc * 32);
#pragma unroll
        for (int p = 0; p < 8; p++) {
            uint32_t br0, br1, br2, br3;
            uint32_t baddr = Bs_sh + ((p * 16 + lrow) * SROW + khalf * 4) * 4 + kc * 32;
            LDMATRIX_X4(br0, br1, br2, br3, baddr);
            mma_f16(acc[2 * p],     a, br0, br2);
            mma_f16(acc[2 * p + 1], a, br1, br3);
        }
    }

    // ---- epilogue ----
    const int r0 = rowBase + warpRow + g;
    const int r1 = r0 + 8;
#pragma unroll
    for (int nt = 0; nt < 16; nt++) {
        const int col = nt * 8 + t4 * 2;
        if (WRITE_SCALED) {
            if (r0 < n) {
                float cs = g_csrc[r0];
                g_tab[r0 * 64 + (col >> 1)] =
                    __floats2half2_rn(fmaxf(acc[nt][0], 0.f) * cs,
                                      fmaxf(acc[nt][1], 0.f) * cs);
            }
            if (r1 < n) {
                float cs = g_csrc[r1];
                g_tab[r1 * 64 + (col >> 1)] =
                    __floats2half2_rn(fmaxf(acc[nt][2], 0.f) * cs,
                                      fmaxf(acc[nt][3], 0.f) * cs);
            }
        } else {
            if (r0 < n)
                *(float2*)&out[r0 * DIMF + col] = make_float2(acc[nt][0], acc[nt][1]);
            if (r1 < n)
                *(float2*)&out[r1 * DIMF + col] = make_float2(acc[nt][2], acc[nt][3]);
        }
    }
}

// ---------------------------------------------------------------------------

#define SMEM_BYTES (2 * 128 * SROW * 4)   // 69632

extern "C" void kernel_launch(void* const* d_in, const int* in_sizes, int n_in,
                              void* d_out, int out_size) {
    const float* node_attr = (const float*)d_in[0];
    const float* W0 = (const float*)d_in[1];
    const float* b0 = (const float*)d_in[2];
    const float* W1 = (const float*)d_in[3];
    const float* b1 = (const float*)d_in[4];
    const float* W2 = (const float*)d_in[5];
    const float* b2 = (const float*)d_in[6];
    const int*   edge = (const int*)d_in[7];

    int n = in_sizes[0] / DIMF;   // 100000
    int E = in_sizes[7] / 2;      // 1600000

    cudaFuncSetAttribute(k_gemm<true>,
                         cudaFuncAttributeMaxDynamicSharedMemorySize, SMEM_BYTES);
    cudaFuncSetAttribute(k_gemm<false>,
                         cudaFuncAttributeMaxDynamicSharedMemorySize, SMEM_BYTES);

    // one-time W conversion (independent of graph work)
    k_prepW<<<dim3(2, 2, 3), 256>>>(W0, W1, W2);

    // zero degrees + allocator (single memset: counter lives at g_deg[2n])
    void* degPtr;
    cudaGetSymbolAddress(&degPtr, g_deg);
    cudaMemsetAsync(degPtr, 0, (2 * n + 1) * sizeof(int));

    k_deg_count<<<cdiv(E, 256), 256>>>(edge, E, n);
    k_offsets<<<cdiv(n, 256), 256>>>(n);
    k_fill<<<cdiv(E, 256), 256>>>(edge, E);

    // layer-1 table
    k_scale<<<cdiv(n * DV4, 256), 256>>>(node_attr, n);

    __half* w16;
    cudaGetSymbolAddress((void**)&w16, g_W16);

    int ggrid = cdiv(n * 16, 256);
    int mgrid = cdiv(n, 128);

    k_gather<<<ggrid, 256>>>(n);
    k_gemm<true><<<mgrid, 256, SMEM_BYTES>>>(w16, b0, nullptr, n);
    k_gather<<<ggrid, 256>>>(n);
    k_gemm<true><<<mgrid, 256, SMEM_BYTES>>>(w16 + DIMF * DIMF, b1, nullptr, n);
    k_gather<<<ggrid, 256>>>(n);
    k_gemm<false><<<mgrid, 256, SMEM_BYTES>>>(w16 + 2 * DIMF * DIMF, b2, (float*)d_out, n);
}